// round 5
// baseline (speedup 1.0000x reference)
#include <cuda_runtime.h>
#include <math.h>

#define N_NODES 50000
#define KNN     8
#define NR      200000   // N * R

// ---------------- scratch (device globals) ----------------
__device__ float g_Wc_enc[64 * 128];                 // [k][ Wd_enc | Wb_enc ]
__device__ float g_W_A[64 * 512];                    // [k][ Am(256) | Alv(256) ]
__device__ float g_W_B[64 * 512];                    // [k][ Bm(256) | Blv(256) ]
__device__ float g_AB1[(size_t)N_NODES * 128];
__device__ float g_h  [(size_t)N_NODES * 64];
__device__ float g_A2 [(size_t)N_NODES * 512];       // own-part (streamed once)
__device__ float g_B2 [(size_t)N_NODES * 512];       // neighbor-part (gathered 8x)

// ---------------- weight prep ----------------
// concat([xi, xj-xi]) @ W == xi @ (W_top - W_bot) + xj @ W_bot
__global__ void prep_weights(const float* __restrict__ We,
                             const float* __restrict__ Wm,
                             const float* __restrict__ Wlv) {
    int idx = blockIdx.x * blockDim.x + threadIdx.x;
    if (idx < 64 * 128) {
        int k = idx >> 7, c = idx & 127;
        g_Wc_enc[idx] = (c < 64) ? We[k * 64 + c] - We[(64 + k) * 64 + c]
                                 : We[(64 + k) * 64 + (c - 64)];
    }
    int i2 = idx - 64 * 128;
    if (i2 >= 0 && i2 < 64 * 512) {
        int k = i2 >> 9, c = i2 & 511;
        float a, b;
        if (c < 256) {
            a = Wm[k * 256 + c] - Wm[(64 + k) * 256 + c];
            b = Wm[(64 + k) * 256 + c];
        } else {
            int j = c - 256;
            a = Wlv[k * 256 + j] - Wlv[(64 + k) * 256 + j];
            b = Wlv[(64 + k) * 256 + j];
        }
        g_W_A[i2] = a;
        g_W_B[i2] = b;
    }
}

// ---------------- tf32 tensor-core GEMM, fragment-native smem ----------------
// C[M,Nout] = X[M,64] @ W[64,Nout] (+bias). 128x64 tile, 256 threads (8 warps).
// Smem holds operands already in mma.m16n8k8 fragment order:
//  afrag[kb][g][lane][slot0..3]  (A: kb=k/8, g=rowgroup/16, slots a0..a3)
//  bfrag[kb][cg][lane][slot0..1] (B: cg=colgroup/8, slots b0,b1)
// Hot loop per warp per kb: 2x LDS.128 + 4x LDS.64 + 8 HMMA.
#define AFR_KB 1028                        // per-kb stride (pad 4 -> staging banks)
#define AFR_SZ (8 * AFR_KB)                // 8224 floats
#define BFR_CG 66                          // per-colgroup stride (pad 2)
#define BFR_KB (8 * BFR_CG + 2)            // 530
#define BFR_SZ (8 * BFR_KB)                // 4240 floats
#define GEMM_SMEM ((AFR_SZ + BFR_SZ) * 4)  // 49856 B

__device__ __forceinline__ float to_tf32(float x) {
    unsigned r;
    asm("cvt.rna.tf32.f32 %0, %1;" : "=r"(r) : "f"(x));
    return __uint_as_float(r);
}

// Stage X[row0..row0+127][0..63] into afrag (zero-fill rows >= M).
__device__ __forceinline__ void stage_x_frag(float* __restrict__ afr,
                                             const float* __restrict__ X,
                                             int row0, int M, int tid) {
    #pragma unroll
    for (int i = 0; i < 8; i++) {
        int f = tid + i * 256, r = f >> 4, c4 = (f & 15) * 4;
        float4 v = make_float4(0.f, 0.f, 0.f, 0.f);
        if (row0 + r < M) v = *(const float4*)(X + (size_t)(row0 + r) * 64 + c4);
        int g = r >> 4, rr = r & 15, qr = rr & 7, hi = rr >> 3;
        int kb = c4 >> 3, half = (c4 >> 2) & 1;
        float* p = afr + kb * AFR_KB + g * 128 + qr * 16 + half * 2 + hi;
        p[0]  = to_tf32(v.x);   // qc=0
        p[4]  = to_tf32(v.y);   // qc=1
        p[8]  = to_tf32(v.z);
        p[12] = to_tf32(v.w);
    }
}

// Stage W[0..63][col0..col0+63] into bfrag.
__device__ __forceinline__ void stage_w_frag(float* __restrict__ bfr,
                                             const float* __restrict__ W,
                                             int col0, int Nout, int tid) {
    #pragma unroll
    for (int i = 0; i < 4; i++) {
        int f = tid + i * 256, k = f >> 4, c4 = (f & 15) * 4;
        float4 v = *(const float4*)(W + (size_t)k * Nout + col0 + c4);
        int kb = k >> 3, qc = k & 3, half = (k >> 2) & 1;
        float* base = bfr + kb * BFR_KB + half;
        float vals[4] = {v.x, v.y, v.z, v.w};
        #pragma unroll
        for (int j = 0; j < 4; j++) {
            int c = c4 + j, cg = c >> 3, qr = c & 7;
            base[cg * BFR_CG + (qr * 4 + qc) * 2] = to_tf32(vals[j]);
        }
    }
}

// 128x64 MMA accumulate from fragment buffers.
__device__ __forceinline__ void mma_tile(const float* __restrict__ afr,
                                         const float* __restrict__ bfr,
                                         float acc[2][4][4],
                                         int wr, int wc, int lane) {
    #pragma unroll
    for (int kb = 0; kb < 8; kb++) {
        float4 a4[2];
        #pragma unroll
        for (int mi = 0; mi < 2; mi++)
            a4[mi] = *(const float4*)(afr + kb * AFR_KB + (wr * 2 + mi) * 128 + lane * 4);
        float2 b2[4];
        #pragma unroll
        for (int ni = 0; ni < 4; ni++)
            b2[ni] = *(const float2*)(bfr + kb * BFR_KB + (wc * 4 + ni) * BFR_CG + lane * 2);
        #pragma unroll
        for (int mi = 0; mi < 2; mi++)
            #pragma unroll
            for (int ni = 0; ni < 4; ni++)
                asm volatile(
                    "mma.sync.aligned.m16n8k8.row.col.f32.tf32.tf32.f32 "
                    "{%0,%1,%2,%3}, {%4,%5,%6,%7}, {%8,%9}, {%0,%1,%2,%3};"
                    : "+f"(acc[mi][ni][0]), "+f"(acc[mi][ni][1]),
                      "+f"(acc[mi][ni][2]), "+f"(acc[mi][ni][3])
                    : "r"(__float_as_uint(a4[mi].x)), "r"(__float_as_uint(a4[mi].y)),
                      "r"(__float_as_uint(a4[mi].z)), "r"(__float_as_uint(a4[mi].w)),
                      "r"(__float_as_uint(b2[ni].x)), "r"(__float_as_uint(b2[ni].y)));
    }
}

__device__ __forceinline__ void epilogue_store(float acc[2][4][4],
                                               float* __restrict__ C,
                                               const float* __restrict__ bias,
                                               int row0, int col0, int M, int Nout,
                                               int wr, int wc, int qr, int qc) {
    #pragma unroll
    for (int mi = 0; mi < 2; mi++) {
        #pragma unroll
        for (int half = 0; half < 2; half++) {
            int row = row0 + wr * 32 + mi * 16 + qr + half * 8;
            if (row < M) {
                #pragma unroll
                for (int ni = 0; ni < 4; ni++) {
                    int col = col0 + wc * 32 + ni * 8 + qc * 2;
                    float2 v;
                    v.x = acc[mi][ni][half * 2 + 0];
                    v.y = acc[mi][ni][half * 2 + 1];
                    if (bias) {
                        float2 bv = *(const float2*)(bias + col);
                        v.x += bv.x; v.y += bv.y;
                    }
                    *(float2*)(C + (size_t)row * Nout + col) = v;
                }
            }
        }
    }
}

__global__ void __launch_bounds__(256)
gemm_tc(const float* __restrict__ X, const float* __restrict__ W,
        float* __restrict__ C, int M, int Nout, const float* __restrict__ bias)
{
    extern __shared__ float sm[];
    float* afr = sm;
    float* bfr = sm + AFR_SZ;
    const int tid  = threadIdx.x;
    const int row0 = blockIdx.x * 128;
    const int col0 = blockIdx.y * 64;

    stage_x_frag(afr, X, row0, M, tid);
    stage_w_frag(bfr, W, col0, Nout, tid);
    __syncthreads();

    const int warp = tid >> 5, lane = tid & 31;
    const int wr = warp >> 1, wc = warp & 1;
    const int qr = lane >> 2, qc = lane & 3;

    float acc[2][4][4];
    #pragma unroll
    for (int mi = 0; mi < 2; mi++)
        #pragma unroll
        for (int ni = 0; ni < 4; ni++)
            #pragma unroll
            for (int t = 0; t < 4; t++) acc[mi][ni][t] = 0.f;

    mma_tile(afr, bfr, acc, wr, wc, lane);
    epilogue_store(acc, C, bias, row0, col0, M, Nout, wr, wc, qr, qc);
}

// ---------------- encoder gather-max + bias + leaky_relu(0.2) ----------------
__global__ void __launch_bounds__(256)
gather_enc(const int* __restrict__ src, const float* __restrict__ b) {
    __shared__ int ss[32];
    int tid = threadIdx.x;
    if (tid < 32) ss[tid] = src[blockIdx.x * 32 + tid];
    __syncthreads();
    int local = tid >> 6;
    int j     = tid & 63;
    int node  = blockIdx.x * 4 + local;
    float a = __ldcs(g_AB1 + (size_t)node * 128 + j);
    float m = -3.4e38f;
    #pragma unroll
    for (int k = 0; k < KNN; k++) {
        int s = ss[local * 8 + k];
        m = fmaxf(m, g_AB1[(size_t)s * 128 + 64 + j]);
    }
    float v = a + m + b[j];
    g_h[(size_t)node * 64 + j] = v > 0.f ? v : 0.2f * v;
}

// ---------------- fused: gather_ml + point_shuffle + reparametrize + decoder GEMM ----
// One block = 32 nodes = 128 z-rows. Gather phase writes z directly into the
// A-fragment buffer (tf32); then 128x64x64 MMA against Wd; epilogue writes out.
__global__ void __launch_bounds__(256)
fused_dec(const int* __restrict__ src, const float* __restrict__ noise,
          const float* __restrict__ bm, const float* __restrict__ blv,
          const float* __restrict__ Wd, const float* __restrict__ bd,
          float* __restrict__ out)
{
    extern __shared__ float sm[];
    float* zfr = sm;            // afrag layout (z is the A operand)
    float* bfr = sm + AFR_SZ;   // Wd fragments
    __shared__ int ss[256];

    const int tid = threadIdx.x;
    const int n0  = blockIdx.x * 32;

    stage_w_frag(bfr, Wd, 0, 64, tid);
    int ei = n0 * KNN + tid;
    ss[tid] = (ei < N_NODES * KNN) ? src[ei] : 0;
    __syncthreads();

    // per-thread channel c = tid (0..255): mean chan c AND logvar chan c
    const float bmv  = bm[tid];
    const float blvv = blv[tid];
    const int r  = tid & 3;
    const int c2 = tid >> 2;                 // z column (k of decoder GEMM)
    const int kb = c2 >> 3, qcz = c2 & 3, halfz = (c2 >> 2) & 1;

    #pragma unroll 2
    for (int nl = 0; nl < 32; nl++) {
        int node = n0 + nl;
        float zval = 0.f;
        if (node < N_NODES) {
            size_t abase = (size_t)node * 512;
            float am  = __ldcs(g_A2 + abase + tid);
            float alv = __ldcs(g_A2 + abase + 256 + tid);
            float mm = -3.4e38f, mlv = -3.4e38f;
            #pragma unroll
            for (int k = 0; k < KNN; k++) {
                size_t sb = (size_t)ss[nl * 8 + k] * 512;
                mm  = fmaxf(mm,  g_B2[sb + tid]);
                mlv = fmaxf(mlv, g_B2[sb + 256 + tid]);
            }
            float zm  = am  + mm  + bmv;
            float zlv = alv + mlv + blvv;
            size_t o = (size_t)(node * 4 + r) * 64 + c2;
            zval = fmaf(__ldcs(noise + o), expf(0.5f * zlv), zm);
        }
        int row = nl * 4 + r;                // 0..127 within tile
        int g = row >> 4, rr = row & 15, qr = rr & 7, hi = rr >> 3;
        zfr[kb * AFR_KB + g * 128 + qr * 16 + qcz * 4 + halfz * 2 + hi] = to_tf32(zval);
    }
    __syncthreads();

    const int warp = tid >> 5, lane = tid & 31;
    const int wr = warp >> 1, wc = warp & 1;
    const int qr = lane >> 2, qc = lane & 3;

    float acc[2][4][4];
    #pragma unroll
    for (int mi = 0; mi < 2; mi++)
        #pragma unroll
        for (int ni = 0; ni < 4; ni++)
            #pragma unroll
            for (int t = 0; t < 4; t++) acc[mi][ni][t] = 0.f;

    mma_tile(zfr, bfr, acc, wr, wc, lane);
    epilogue_store(acc, out, bd, blockIdx.x * 128, 0, NR, 64, wr, wc, qr, qc);
}

// ---------------- launch ----------------
extern "C" void kernel_launch(void* const* d_in, const int* in_sizes, int n_in,
                              void* d_out, int out_size) {
    const float* x     = (const float*)d_in[0];
    const int*   src   = (const int*)  d_in[1];
    const float* noise = (const float*)d_in[3];
    const float* We    = (const float*)d_in[4];
    const float* be    = (const float*)d_in[5];
    const float* Wm    = (const float*)d_in[6];
    const float* bm    = (const float*)d_in[7];
    const float* Wlv   = (const float*)d_in[8];
    const float* blv   = (const float*)d_in[9];
    const float* Wd    = (const float*)d_in[10];
    const float* bd    = (const float*)d_in[11];
    float* out = (float*)d_out;

    float *pWcE, *pWA, *pWB, *pAB1, *pH, *pA2, *pB2;
    cudaGetSymbolAddress((void**)&pWcE, g_Wc_enc);
    cudaGetSymbolAddress((void**)&pWA,  g_W_A);
    cudaGetSymbolAddress((void**)&pWB,  g_W_B);
    cudaGetSymbolAddress((void**)&pAB1, g_AB1);
    cudaGetSymbolAddress((void**)&pH,   g_h);
    cudaGetSymbolAddress((void**)&pA2,  g_A2);
    cudaGetSymbolAddress((void**)&pB2,  g_B2);

    cudaFuncSetAttribute(gemm_tc,   cudaFuncAttributeMaxDynamicSharedMemorySize, GEMM_SMEM);
    cudaFuncSetAttribute(fused_dec, cudaFuncAttributeMaxDynamicSharedMemorySize, GEMM_SMEM);

    // 1. combined weights
    prep_weights<<<160, 256>>>(We, Wm, Wlv);
    // 2. AB1 = x @ [Wd_enc | Wb_enc]   (50000 x 128)
    gemm_tc<<<dim3(391, 2), 256, GEMM_SMEM>>>(x, pWcE, pAB1, N_NODES, 128, nullptr);
    // 3. h = leaky(A + max_k B[src] + b)
    gather_enc<<<12500, 256>>>(src, be);
    // 4a. A2 = h @ [Am|Alv]   (own-part)
    gemm_tc<<<dim3(391, 8), 256, GEMM_SMEM>>>(pH, pWA, pA2, N_NODES, 512, nullptr);
    // 4b. B2 = h @ [Bm|Blv]   (neighbor-part)
    gemm_tc<<<dim3(391, 8), 256, GEMM_SMEM>>>(pH, pWB, pB2, N_NODES, 512, nullptr);
    // 5. fused gather-max + shuffle + reparametrize + decoder
    fused_dec<<<1563, 256, GEMM_SMEM>>>(src, noise, bm, blv, Wd, bd, out);
}

// round 6
// speedup vs baseline: 1.3149x; 1.3149x over previous
#include <cuda_runtime.h>
#include <math.h>

#define N_NODES 50000
#define KNN     8
#define NR      200000   // N * R

// ---------------- scratch (device globals) ----------------
__device__ float g_Wc_enc[64 * 128];                 // [k][ Wd_enc | Wb_enc ]
__device__ float g_W_A[64 * 512];                    // [k][ Am(256) | Alv(256) ]
__device__ float g_W_B[64 * 512];                    // [k][ Bm(256) | Blv(256) ]
__device__ float g_AB1[(size_t)N_NODES * 128];
__device__ float g_h  [(size_t)N_NODES * 64];
__device__ float g_A2 [(size_t)N_NODES * 512];       // own-part (streamed once)
__device__ float g_B2 [(size_t)N_NODES * 512];       // neighbor-part (gathered 8x)
__device__ float g_z  [(size_t)NR * 64];

// ---------------- weight prep ----------------
// concat([xi, xj-xi]) @ W == xi @ (W_top - W_bot) + xj @ W_bot
__global__ void prep_weights(const float* __restrict__ We,
                             const float* __restrict__ Wm,
                             const float* __restrict__ Wlv) {
    int idx = blockIdx.x * blockDim.x + threadIdx.x;
    if (idx < 64 * 128) {
        int k = idx >> 7, c = idx & 127;
        g_Wc_enc[idx] = (c < 64) ? We[k * 64 + c] - We[(64 + k) * 64 + c]
                                 : We[(64 + k) * 64 + (c - 64)];
    }
    int i2 = idx - 64 * 128;
    if (i2 >= 0 && i2 < 64 * 512) {
        int k = i2 >> 9, c = i2 & 511;
        float a, b;
        if (c < 256) {
            a = Wm[k * 256 + c] - Wm[(64 + k) * 256 + c];
            b = Wm[(64 + k) * 256 + c];
        } else {
            int j = c - 256;
            a = Wlv[k * 256 + j] - Wlv[(64 + k) * 256 + j];
            b = Wlv[(64 + k) * 256 + j];
        }
        g_W_A[i2] = a;
        g_W_B[i2] = b;
    }
}

// ---------------- tf32 tensor-core GEMM, column-looped ----------------
// C[M,Nout] = X[M,64] @ W[64,Nout] (+bias).
// Block: 128 rows x (NT*64) cols. X staged ONCE; a-frags hoisted to registers
// and reused across NT column tiles; per-tile hot loop touches smem only for
// b-frags (8 scalar LDS per kb per warp).
#define XS 68
#define WS 68
#define GEMM_SMEM ((128 * XS + 64 * WS) * 4)   // 52224 B

__device__ __forceinline__ float to_tf32(float x) {
    unsigned r;
    asm("cvt.rna.tf32.f32 %0, %1;" : "=r"(r) : "f"(x));
    return __uint_as_float(r);
}

template<int NT>
__global__ void __launch_bounds__(256, 2)
gemm_cl(const float* __restrict__ X, const float* __restrict__ W,
        float* __restrict__ C, int M, int Nout, const float* __restrict__ bias)
{
    extern __shared__ float sm[];
    float* xs = sm;                 // [128][XS]  X tile (tf32)
    float* ws = sm + 128 * XS;      // [64][WS]   current W column tile (tf32)

    const int tid  = threadIdx.x;
    const int row0 = blockIdx.x * 128;

    // stage X once: 128 rows x 64 cols
    #pragma unroll
    for (int i = 0; i < 8; i++) {
        int f  = tid + i * 256;
        int r  = f >> 4;
        int c4 = (f & 15) * 4;
        float4 v = make_float4(0.f, 0.f, 0.f, 0.f);
        if (row0 + r < M) v = *(const float4*)(X + (size_t)(row0 + r) * 64 + c4);
        float* p = xs + r * XS + c4;
        p[0] = to_tf32(v.x); p[1] = to_tf32(v.y);
        p[2] = to_tf32(v.z); p[3] = to_tf32(v.w);
    }
    __syncthreads();

    const int warp = tid >> 5;
    const int lane = tid & 31;
    const int wr   = warp >> 1;          // 0..3 -> rows wr*32
    const int wc   = warp & 1;           // 0..1 -> cols wc*32
    const int qr   = lane >> 2;          // 0..7
    const int qc   = lane & 3;           // 0..3

    // hoist A-fragments for the whole K=64 into registers (reused NT times)
    unsigned areg[8][2][4];
    #pragma unroll
    for (int kb = 0; kb < 8; kb++) {
        #pragma unroll
        for (int mi = 0; mi < 2; mi++) {
            const float* p = xs + (wr * 32 + mi * 16 + qr) * XS + kb * 8 + qc;
            areg[kb][mi][0] = __float_as_uint(p[0]);
            areg[kb][mi][1] = __float_as_uint(p[8 * XS]);
            areg[kb][mi][2] = __float_as_uint(p[4]);
            areg[kb][mi][3] = __float_as_uint(p[8 * XS + 4]);
        }
    }

    #pragma unroll 1
    for (int t = 0; t < NT; t++) {
        const int col0 = (blockIdx.y * NT + t) * 64;

        // stage W column tile
        #pragma unroll
        for (int i = 0; i < 4; i++) {
            int f  = tid + i * 256;
            int r  = f >> 4;
            int c4 = (f & 15) * 4;
            float4 v = *(const float4*)(W + (size_t)r * Nout + col0 + c4);
            float* p = ws + r * WS + c4;
            p[0] = to_tf32(v.x); p[1] = to_tf32(v.y);
            p[2] = to_tf32(v.z); p[3] = to_tf32(v.w);
        }
        __syncthreads();

        float acc[2][4][4];
        #pragma unroll
        for (int mi = 0; mi < 2; mi++)
            #pragma unroll
            for (int ni = 0; ni < 4; ni++)
                #pragma unroll
                for (int s = 0; s < 4; s++) acc[mi][ni][s] = 0.f;

        #pragma unroll
        for (int kb = 0; kb < 8; kb++) {
            unsigned b[4][2];
            #pragma unroll
            for (int ni = 0; ni < 4; ni++) {
                const float* p = ws + (kb * 8 + qc) * WS + wc * 32 + ni * 8 + qr;
                b[ni][0] = __float_as_uint(p[0]);
                b[ni][1] = __float_as_uint(p[4 * WS]);
            }
            #pragma unroll
            for (int mi = 0; mi < 2; mi++)
                #pragma unroll
                for (int ni = 0; ni < 4; ni++)
                    asm volatile(
                        "mma.sync.aligned.m16n8k8.row.col.f32.tf32.tf32.f32 "
                        "{%0,%1,%2,%3}, {%4,%5,%6,%7}, {%8,%9}, {%0,%1,%2,%3};"
                        : "+f"(acc[mi][ni][0]), "+f"(acc[mi][ni][1]),
                          "+f"(acc[mi][ni][2]), "+f"(acc[mi][ni][3])
                        : "r"(areg[kb][mi][0]), "r"(areg[kb][mi][1]),
                          "r"(areg[kb][mi][2]), "r"(areg[kb][mi][3]),
                          "r"(b[ni][0]), "r"(b[ni][1]));
        }
        __syncthreads();   // all warps done reading ws before next restage

        // epilogue
        #pragma unroll
        for (int mi = 0; mi < 2; mi++) {
            #pragma unroll
            for (int half = 0; half < 2; half++) {
                int row = row0 + wr * 32 + mi * 16 + qr + half * 8;
                if (row < M) {
                    #pragma unroll
                    for (int ni = 0; ni < 4; ni++) {
                        int col = col0 + wc * 32 + ni * 8 + qc * 2;
                        float2 v;
                        v.x = acc[mi][ni][half * 2 + 0];
                        v.y = acc[mi][ni][half * 2 + 1];
                        if (bias) {
                            float2 bv = *(const float2*)(bias + col);
                            v.x += bv.x; v.y += bv.y;
                        }
                        *(float2*)(C + (size_t)row * Nout + col) = v;
                    }
                }
            }
        }
    }
}

// ---------------- encoder gather-max + bias + leaky_relu(0.2) ----------------
__global__ void __launch_bounds__(256)
gather_enc(const int* __restrict__ src, const float* __restrict__ b) {
    __shared__ int ss[32];
    int tid = threadIdx.x;
    if (tid < 32) ss[tid] = src[blockIdx.x * 32 + tid];
    __syncthreads();
    int local = tid >> 6;
    int j     = tid & 63;
    int node  = blockIdx.x * 4 + local;
    float a = __ldcs(g_AB1 + (size_t)node * 128 + j);
    float m = -3.4e38f;
    #pragma unroll
    for (int k = 0; k < KNN; k++) {
        int s = ss[local * 8 + k];
        m = fmaxf(m, g_AB1[(size_t)s * 128 + 64 + j]);
    }
    float v = a + m + b[j];
    g_h[(size_t)node * 64 + j] = v > 0.f ? v : 0.2f * v;
}

// ---------------- mean/logvar gather-max + shuffle + reparametrize ----------------
__global__ void __launch_bounds__(256)
gather_ml(const int* __restrict__ src, const float* __restrict__ noise,
          const float* __restrict__ bm, const float* __restrict__ blv) {
    __shared__ int ss[KNN];
    int tid  = threadIdx.x;
    int node = blockIdx.x;
    if (tid < KNN) ss[tid] = src[node * KNN + tid];
    __syncthreads();
    size_t abase = (size_t)node * 512;
    float am  = __ldcs(g_A2 + abase + tid);          // streamed: protect B2 in L2
    float alv = __ldcs(g_A2 + abase + 256 + tid);
    float mm = -3.4e38f, mlv = -3.4e38f;
    #pragma unroll
    for (int k = 0; k < KNN; k++) {
        size_t sb = (size_t)ss[k] * 512;
        mm  = fmaxf(mm,  g_B2[sb + tid]);
        mlv = fmaxf(mlv, g_B2[sb + 256 + tid]);
    }
    float zm  = am  + mm  + bm[tid];
    float zlv = alv + mlv + blv[tid];
    int r  = tid & 3;
    int c2 = tid >> 2;
    size_t o = (size_t)(node * 4 + r) * 64 + c2;
    float nz = __ldcs(noise + o);
    g_z[o] = fmaf(nz, expf(0.5f * zlv), zm);
}

// ---------------- launch ----------------
extern "C" void kernel_launch(void* const* d_in, const int* in_sizes, int n_in,
                              void* d_out, int out_size) {
    const float* x     = (const float*)d_in[0];
    const int*   src   = (const int*)  d_in[1];
    const float* noise = (const float*)d_in[3];
    const float* We    = (const float*)d_in[4];
    const float* be    = (const float*)d_in[5];
    const float* Wm    = (const float*)d_in[6];
    const float* bm    = (const float*)d_in[7];
    const float* Wlv   = (const float*)d_in[8];
    const float* blv   = (const float*)d_in[9];
    const float* Wd    = (const float*)d_in[10];
    const float* bd    = (const float*)d_in[11];
    float* out = (float*)d_out;

    float *pWcE, *pWA, *pWB, *pAB1, *pH, *pA2, *pB2, *pZ;
    cudaGetSymbolAddress((void**)&pWcE, g_Wc_enc);
    cudaGetSymbolAddress((void**)&pWA,  g_W_A);
    cudaGetSymbolAddress((void**)&pWB,  g_W_B);
    cudaGetSymbolAddress((void**)&pAB1, g_AB1);
    cudaGetSymbolAddress((void**)&pH,   g_h);
    cudaGetSymbolAddress((void**)&pA2,  g_A2);
    cudaGetSymbolAddress((void**)&pB2,  g_B2);
    cudaGetSymbolAddress((void**)&pZ,   g_z);

    cudaFuncSetAttribute(gemm_cl<1>, cudaFuncAttributeMaxDynamicSharedMemorySize, GEMM_SMEM);
    cudaFuncSetAttribute(gemm_cl<2>, cudaFuncAttributeMaxDynamicSharedMemorySize, GEMM_SMEM);
    cudaFuncSetAttribute(gemm_cl<4>, cudaFuncAttributeMaxDynamicSharedMemorySize, GEMM_SMEM);

    // 1. combined weights
    prep_weights<<<160, 256>>>(We, Wm, Wlv);
    // 2. AB1 = x @ [Wd_enc | Wb_enc]   (50000 x 128): NT=2, X staged once
    gemm_cl<2><<<dim3(391, 1), 256, GEMM_SMEM>>>(x, pWcE, pAB1, N_NODES, 128, nullptr);
    // 3. h = leaky(A + max_k B[src] + b)
    gather_enc<<<12500, 256>>>(src, be);
    // 4a. A2 = h @ [Am|Alv]  (50000 x 512): NT=4, grid.y=2
    gemm_cl<4><<<dim3(391, 2), 256, GEMM_SMEM>>>(pH, pWA, pA2, N_NODES, 512, nullptr);
    // 4b. B2 = h @ [Bm|Blv]  (50000 x 512)
    gemm_cl<4><<<dim3(391, 2), 256, GEMM_SMEM>>>(pH, pWB, pB2, N_NODES, 512, nullptr);
    // 5. gather-max x2 + shuffle + reparametrize -> z (200000 x 64)
    gather_ml<<<N_NODES, 256>>>(src, noise, bm, blv);
    // 6. out = z @ W_dec + b_dec
    gemm_cl<1><<<dim3(1563, 1), 256, GEMM_SMEM>>>(pZ, Wd, out, NR, 64, bd);
}

// round 7
// speedup vs baseline: 1.3499x; 1.0267x over previous
#include <cuda_runtime.h>
#include <math.h>

#define N_NODES 50000
#define KNN     8
#define NR      200000   // N * R

// ---------------- scratch (device globals) ----------------
__device__ float g_Wc_enc[64 * 128];                 // tf32-rounded [k][ Wd_enc | Wb_enc ]
__device__ float g_W_A[64 * 512];                    // tf32 [k][ Am(256) | Alv(256) ]
__device__ float g_W_B[64 * 512];                    // tf32 [k][ Bm(256) | Blv(256) ]
__device__ float g_Wdt[64 * 64];                     // tf32 decoder weights
__device__ float g_AB1[(size_t)N_NODES * 128];
__device__ float g_h  [(size_t)N_NODES * 64];        // tf32-rounded at producer
__device__ float g_A2 [(size_t)N_NODES * 512];       // own-part (streamed once)
__device__ float g_B2 [(size_t)N_NODES * 512];       // neighbor-part (gathered 8x)
__device__ float g_z  [(size_t)NR * 64];             // tf32-rounded at producer

__device__ __forceinline__ float to_tf32(float x) {
    unsigned r;
    asm("cvt.rna.tf32.f32 %0, %1;" : "=r"(r) : "f"(x));
    return __uint_as_float(r);
}

// ---------------- weight prep (outputs pre-rounded to tf32) ----------------
// concat([xi, xj-xi]) @ W == xi @ (W_top - W_bot) + xj @ W_bot
__global__ void prep_weights(const float* __restrict__ We,
                             const float* __restrict__ Wm,
                             const float* __restrict__ Wlv,
                             const float* __restrict__ Wd) {
    int idx = blockIdx.x * blockDim.x + threadIdx.x;
    if (idx < 64 * 128) {
        int k = idx >> 7, c = idx & 127;
        float v = (c < 64) ? We[k * 64 + c] - We[(64 + k) * 64 + c]
                           : We[(64 + k) * 64 + (c - 64)];
        g_Wc_enc[idx] = to_tf32(v);
    }
    int i2 = idx - 64 * 128;
    if (i2 >= 0 && i2 < 64 * 512) {
        int k = i2 >> 9, c = i2 & 511;
        float a, b;
        if (c < 256) {
            a = Wm[k * 256 + c] - Wm[(64 + k) * 256 + c];
            b = Wm[(64 + k) * 256 + c];
        } else {
            int j = c - 256;
            a = Wlv[k * 256 + j] - Wlv[(64 + k) * 256 + j];
            b = Wlv[(64 + k) * 256 + j];
        }
        g_W_A[i2] = to_tf32(a);
        g_W_B[i2] = to_tf32(b);
    }
    int i3 = idx - 64 * 128 - 64 * 512;
    if (i3 >= 0 && i3 < 64 * 64) g_Wdt[i3] = to_tf32(Wd[i3]);
}

// ---------------- tf32 tensor-core GEMM, cp.async double-buffered ----------------
// C[M,Nout] = X[M,64] @ W[64,Nout] (+bias). W must be tf32-pre-rounded.
// Block: 128 rows x (NT*64) cols. X staged once; a-frags hoisted to registers.
// W column tiles prefetched via cp.async into alternating buffers while the
// previous tile is MMA'd.
#define XS 68
#define WS 72   // bank = qc*8+qr -> conflict-free b-frag LDS
#define GEMM_SMEM ((128 * XS + 2 * 64 * WS) * 4)   // 71680 B

__device__ __forceinline__ void cp16(unsigned dst, const void* src) {
    asm volatile("cp.async.ca.shared.global [%0], [%1], 16;" :: "r"(dst), "l"(src));
}

template<int NT>
__global__ void __launch_bounds__(256, 2)
gemm_cl(const float* __restrict__ X, const float* __restrict__ W,
        float* __restrict__ C, int M, int Nout, const float* __restrict__ bias)
{
    extern __shared__ float sm[];
    float* xs  = sm;                       // [128][XS]
    float* wsb[2] = { sm + 128 * XS, sm + 128 * XS + 64 * WS };
    const unsigned ws_u0 = (unsigned)__cvta_generic_to_shared(wsb[0]);
    const unsigned ws_u1 = (unsigned)__cvta_generic_to_shared(wsb[1]);

    const int tid  = threadIdx.x;
    const int row0 = blockIdx.x * 128;

    // prefetch W tile 0 (async, overlaps X staging)
    {
        const int col0 = blockIdx.y * NT * 64;
        #pragma unroll
        for (int i = 0; i < 4; i++) {
            int f = tid + i * 256, r = f >> 4, c4 = (f & 15) * 4;
            cp16(ws_u0 + (unsigned)(r * WS + c4) * 4,
                 W + (size_t)r * Nout + col0 + c4);
        }
        asm volatile("cp.async.commit_group;");
    }

    // stage X once (tf32 round; idempotent if already rounded)
    #pragma unroll
    for (int i = 0; i < 8; i++) {
        int f  = tid + i * 256;
        int r  = f >> 4;
        int c4 = (f & 15) * 4;
        float4 v = make_float4(0.f, 0.f, 0.f, 0.f);
        if (row0 + r < M) v = *(const float4*)(X + (size_t)(row0 + r) * 64 + c4);
        float* p = xs + r * XS + c4;
        p[0] = to_tf32(v.x); p[1] = to_tf32(v.y);
        p[2] = to_tf32(v.z); p[3] = to_tf32(v.w);
    }
    __syncthreads();

    const int warp = tid >> 5;
    const int lane = tid & 31;
    const int wr   = warp >> 1;
    const int wc   = warp & 1;
    const int qr   = lane >> 2;
    const int qc   = lane & 3;

    // hoist A-fragments (whole K=64) into registers, reused across NT tiles
    unsigned areg[8][2][4];
    #pragma unroll
    for (int kb = 0; kb < 8; kb++) {
        #pragma unroll
        for (int mi = 0; mi < 2; mi++) {
            const float* p = xs + (wr * 32 + mi * 16 + qr) * XS + kb * 8 + qc;
            areg[kb][mi][0] = __float_as_uint(p[0]);
            areg[kb][mi][1] = __float_as_uint(p[8 * XS]);
            areg[kb][mi][2] = __float_as_uint(p[4]);
            areg[kb][mi][3] = __float_as_uint(p[8 * XS + 4]);
        }
    }

    for (int t = 0; t < NT; t++) {
        // prefetch tile t+1 into the other buffer
        if (t + 1 < NT) {
            const int coln = (blockIdx.y * NT + t + 1) * 64;
            unsigned ws_n = ((t + 1) & 1) ? ws_u1 : ws_u0;
            #pragma unroll
            for (int i = 0; i < 4; i++) {
                int f = tid + i * 256, r = f >> 4, c4 = (f & 15) * 4;
                cp16(ws_n + (unsigned)(r * WS + c4) * 4,
                     W + (size_t)r * Nout + coln + c4);
            }
            asm volatile("cp.async.commit_group;");
            asm volatile("cp.async.wait_group 1;");
        } else {
            asm volatile("cp.async.wait_group 0;");
        }
        __syncthreads();   // tile t visible to all warps

        const float* ws = wsb[t & 1];
        float acc[2][4][4];
        #pragma unroll
        for (int mi = 0; mi < 2; mi++)
            #pragma unroll
            for (int ni = 0; ni < 4; ni++)
                #pragma unroll
                for (int s = 0; s < 4; s++) acc[mi][ni][s] = 0.f;

        #pragma unroll
        for (int kb = 0; kb < 8; kb++) {
            unsigned b[4][2];
            #pragma unroll
            for (int ni = 0; ni < 4; ni++) {
                const float* p = ws + (kb * 8 + qc) * WS + wc * 32 + ni * 8 + qr;
                b[ni][0] = __float_as_uint(p[0]);
                b[ni][1] = __float_as_uint(p[4 * WS]);
            }
            #pragma unroll
            for (int mi = 0; mi < 2; mi++)
                #pragma unroll
                for (int ni = 0; ni < 4; ni++)
                    asm volatile(
                        "mma.sync.aligned.m16n8k8.row.col.f32.tf32.tf32.f32 "
                        "{%0,%1,%2,%3}, {%4,%5,%6,%7}, {%8,%9}, {%0,%1,%2,%3};"
                        : "+f"(acc[mi][ni][0]), "+f"(acc[mi][ni][1]),
                          "+f"(acc[mi][ni][2]), "+f"(acc[mi][ni][3])
                        : "r"(areg[kb][mi][0]), "r"(areg[kb][mi][1]),
                          "r"(areg[kb][mi][2]), "r"(areg[kb][mi][3]),
                          "r"(b[ni][0]), "r"(b[ni][1]));
        }
        __syncthreads();   // all reads of ws[t&1] done before t+1 re-stages it

        // epilogue
        const int col0 = (blockIdx.y * NT + t) * 64;
        #pragma unroll
        for (int mi = 0; mi < 2; mi++) {
            #pragma unroll
            for (int half = 0; half < 2; half++) {
                int row = row0 + wr * 32 + mi * 16 + qr + half * 8;
                if (row < M) {
                    #pragma unroll
                    for (int ni = 0; ni < 4; ni++) {
                        int col = col0 + wc * 32 + ni * 8 + qc * 2;
                        float2 v;
                        v.x = acc[mi][ni][half * 2 + 0];
                        v.y = acc[mi][ni][half * 2 + 1];
                        if (bias) {
                            float2 bv = *(const float2*)(bias + col);
                            v.x += bv.x; v.y += bv.y;
                        }
                        *(float2*)(C + (size_t)row * Nout + col) = v;
                    }
                }
            }
        }
    }
}

// ---------------- encoder gather-max + bias + leaky_relu(0.2) ----------------
__global__ void __launch_bounds__(256)
gather_enc(const int* __restrict__ src, const float* __restrict__ b) {
    __shared__ int ss[32];
    int tid = threadIdx.x;
    if (tid < 32) ss[tid] = src[blockIdx.x * 32 + tid];
    __syncthreads();
    int local = tid >> 6;
    int j     = tid & 63;
    int node  = blockIdx.x * 4 + local;
    float a = __ldcs(g_AB1 + (size_t)node * 128 + j);
    float m = -3.4e38f;
    #pragma unroll
    for (int k = 0; k < KNN; k++) {
        int s = ss[local * 8 + k];
        m = fmaxf(m, g_AB1[(size_t)s * 128 + 64 + j]);
    }
    float v = a + m + b[j];
    v = v > 0.f ? v : 0.2f * v;
    g_h[(size_t)node * 64 + j] = to_tf32(v);   // pre-round for raw-copy GEMM staging
}

// ---------------- mean/logvar gather-max + shuffle + reparametrize ----------------
__global__ void __launch_bounds__(256)
gather_ml(const int* __restrict__ src, const float* __restrict__ noise,
          const float* __restrict__ bm, const float* __restrict__ blv) {
    __shared__ int ss[KNN];
    int tid  = threadIdx.x;
    int node = blockIdx.x;
    if (tid < KNN) ss[tid] = src[node * KNN + tid];
    __syncthreads();
    size_t abase = (size_t)node * 512;
    float am  = __ldcs(g_A2 + abase + tid);          // streamed: protect B2 in L2
    float alv = __ldcs(g_A2 + abase + 256 + tid);
    float mm = -3.4e38f, mlv = -3.4e38f;
    #pragma unroll
    for (int k = 0; k < KNN; k++) {
        size_t sb = (size_t)ss[k] * 512;
        mm  = fmaxf(mm,  g_B2[sb + tid]);
        mlv = fmaxf(mlv, g_B2[sb + 256 + tid]);
    }
    float zm  = am  + mm  + bm[tid];
    float zlv = alv + mlv + blv[tid];
    int r  = tid & 3;
    int c2 = tid >> 2;
    size_t o = (size_t)(node * 4 + r) * 64 + c2;
    float nz = __ldcs(noise + o);
    g_z[o] = to_tf32(fmaf(nz, expf(0.5f * zlv), zm));
}

// ---------------- launch ----------------
extern "C" void kernel_launch(void* const* d_in, const int* in_sizes, int n_in,
                              void* d_out, int out_size) {
    const float* x     = (const float*)d_in[0];
    const int*   src   = (const int*)  d_in[1];
    const float* noise = (const float*)d_in[3];
    const float* We    = (const float*)d_in[4];
    const float* be    = (const float*)d_in[5];
    const float* Wm    = (const float*)d_in[6];
    const float* bm    = (const float*)d_in[7];
    const float* Wlv   = (const float*)d_in[8];
    const float* blv   = (const float*)d_in[9];
    const float* Wd    = (const float*)d_in[10];
    const float* bd    = (const float*)d_in[11];
    float* out = (float*)d_out;

    float *pWcE, *pWA, *pWB, *pWdt, *pAB1, *pH, *pA2, *pB2, *pZ;
    cudaGetSymbolAddress((void**)&pWcE, g_Wc_enc);
    cudaGetSymbolAddress((void**)&pWA,  g_W_A);
    cudaGetSymbolAddress((void**)&pWB,  g_W_B);
    cudaGetSymbolAddress((void**)&pWdt, g_Wdt);
    cudaGetSymbolAddress((void**)&pAB1, g_AB1);
    cudaGetSymbolAddress((void**)&pH,   g_h);
    cudaGetSymbolAddress((void**)&pA2,  g_A2);
    cudaGetSymbolAddress((void**)&pB2,  g_B2);
    cudaGetSymbolAddress((void**)&pZ,   g_z);

    cudaFuncSetAttribute(gemm_cl<1>, cudaFuncAttributeMaxDynamicSharedMemorySize, GEMM_SMEM);
    cudaFuncSetAttribute(gemm_cl<2>, cudaFuncAttributeMaxDynamicSharedMemorySize, GEMM_SMEM);
    cudaFuncSetAttribute(gemm_cl<4>, cudaFuncAttributeMaxDynamicSharedMemorySize, GEMM_SMEM);

    // 1. combined weights (pre-rounded to tf32)
    prep_weights<<<176, 256>>>(We, Wm, Wlv, Wd);
    // 2. AB1 = x @ [Wd_enc | Wb_enc]   (50000 x 128)
    gemm_cl<2><<<dim3(391, 1), 256, GEMM_SMEM>>>(x, pWcE, pAB1, N_NODES, 128, nullptr);
    // 3. h = leaky(A + max_k B[src] + b)   (tf32-rounded)
    gather_enc<<<12500, 256>>>(src, be);
    // 4a. A2 = h @ [Am|Alv]  (50000 x 512)
    gemm_cl<4><<<dim3(391, 2), 256, GEMM_SMEM>>>(pH, pWA, pA2, N_NODES, 512, nullptr);
    // 4b. B2 = h @ [Bm|Blv]  (50000 x 512)
    gemm_cl<4><<<dim3(391, 2), 256, GEMM_SMEM>>>(pH, pWB, pB2, N_NODES, 512, nullptr);
    // 5. gather-max x2 + shuffle + reparametrize -> z (200000 x 64, tf32-rounded)
    gather_ml<<<N_NODES, 256>>>(src, noise, bm, blv);
    // 6. out = z @ W_dec + b_dec
    gemm_cl<1><<<dim3(1563, 1), 256, GEMM_SMEM>>>(pZ, pWdt, out, NR, 64, bd);
}